// round 4
// baseline (speedup 1.0000x reference)
#include <cuda_runtime.h>
#include <cstdint>

// Problem constants
#define NN    8192
#define NP1   8193
#define AB    16384ULL                    // A_low base (floats)
#define MM    67125249ULL                 // NP1*NP1 floats per matrix
#define AUB   (AB + MM)                   // A_up base
#define LR0   134258689ULL                // A_up last-row start = AUB + NN*NP1
#define T_TOT 134266882ULL                // total output floats

// Flat patch-work segments (one store per thread):
//   [0, 16384)                : conc_low | conc_up head
//   [16384, 24577)            : A_up last row, cols 0..8192 (col 8192 -> 1.0)
//   [24577, 32770)            : A_low diagonal, k = 0..8192 (k=8192 -> 1.0)
//   [32770, 40962)            : A_up diagonal,  k = 0..8191
#define W_HEAD   16384
#define W_LROW   (W_HEAD + NP1)           // 24577
#define W_DLOW   (W_LROW + NP1)           // 32770
#define W_TOT    (W_DLOW + NN)            // 40962

#define THREADS 256

__global__ void __launch_bounds__(THREADS) relu_relax_patch(
        const float* __restrict__ lower,
        const float* __restrict__ upper,
        const float* __restrict__ alphas,
        float* __restrict__ out) {
    const int w = blockIdx.x * THREADS + threadIdx.x;
    if (w >= W_TOT) return;

    size_t pos;
    float  val;

    if (w < W_HEAD) {
        // conc_low / conc_up vectors
        const int i = w & (NN - 1);
        const float l = lower[i];
        const float u = upper[i];
        if (w < NN) {
            const float a = fminf(fmaxf(alphas[i], 0.f), 1.f);
            const bool active   = (u > 0.f) && (l >= 0.f);
            const bool unstable = (u > 0.f) && (l < 0.f);
            val = active ? l : (unstable ? a * l : 0.f);
        } else {
            val = (u > 0.f) ? u : 0.f;
        }
        pos = (size_t)w;
    } else if (w < W_LROW) {
        // A_up last row (bias_up), col NN -> 1.0
        const int col = w - W_HEAD;
        if (col == NN) {
            val = 1.f;
        } else {
            const float l = lower[col];
            const float u = upper[col];
            const bool unstable = (u > 0.f) && (l < 0.f);
            const float d = u - l;
            const float lam = u / ((d == 0.f) ? 1.f : d);
            val = unstable ? (-lam * l) : 0.f;
        }
        pos = LR0 + (size_t)col;
    } else if (w < W_DLOW) {
        // A_low diagonal
        const int k = w - W_LROW;
        if (k == NN) {
            val = 1.f;
        } else {
            const float l = lower[k];
            const float u = upper[k];
            const bool active   = (u > 0.f) && (l >= 0.f);
            const bool unstable = (u > 0.f) && (l < 0.f);
            const float a = fminf(fmaxf(alphas[k], 0.f), 1.f);
            val = active ? 1.f : (unstable ? a : 0.f);
        }
        pos = AB + (size_t)k * (size_t)(NP1 + 1);
    } else {
        // A_up diagonal (k = 0..NN-1; k = NN lives in the last row segment)
        const int k = w - W_DLOW;
        const float l = lower[k];
        const float u = upper[k];
        const bool active   = (u > 0.f) && (l >= 0.f);
        const bool unstable = (u > 0.f) && (l < 0.f);
        const float d = u - l;
        const float lam = u / ((d == 0.f) ? 1.f : d);
        val = active ? 1.f : (unstable ? lam : 0.f);
        pos = AUB + (size_t)k * (size_t)(NP1 + 1);
    }

    out[pos] = val;
}

extern "C" void kernel_launch(void* const* d_in, const int* in_sizes, int n_in,
                              void* d_out, int out_size) {
    const float* lower  = (const float*)d_in[0];
    const float* upper  = (const float*)d_in[1];
    const float* alphas = (const float*)d_in[2];
    float* out = (float*)d_out;

    // Zero only what the patch kernel doesn't fully write:
    // floats [2N, LR0)  == A_low and A_up minus A_up's last row.
    cudaMemsetAsync((char*)d_out + AB * 4, 0, (LR0 - AB) * 4, 0);

    const int blocks = (W_TOT + THREADS - 1) / THREADS;   // 161
    relu_relax_patch<<<blocks, THREADS>>>(lower, upper, alphas, out);
}

// round 5
// speedup vs baseline: 1.4640x; 1.4640x over previous
#include <cuda_runtime.h>
#include <cstdint>

// Problem constants
#define NN    8192
#define NP1   8193
#define AB    16384ULL                    // A_low base (floats)
#define MM    67125249ULL                 // NP1*NP1 floats per matrix
#define AUB   (AB + MM)                   // A_up base
#define LR0   134258689ULL                // A_up last-row start = AUB + NN*NP1

// Flat patch-work segments (one store per thread):
//   [0, 16384)      : conc_low | conc_up head
//   [16384, 24577)  : A_up last row, cols 0..8192 (col 8192 -> 1.0)
//   [24577, 32770)  : A_low diagonal, k = 0..8192 (k = 8192 -> 1.0)
//   [32770, 40962)  : A_up diagonal,  k = 0..8191
#define W_HEAD   16384
#define W_LROW   (W_HEAD + NP1)           // 24577
#define W_DLOW   (W_LROW + NP1)           // 32770
#define W_TOT    (W_DLOW + NN)            // 40962

#define THREADS 512

__global__ void __launch_bounds__(THREADS) relu_relax_patch(
        const float* __restrict__ lower,
        const float* __restrict__ upper,
        const float* __restrict__ alphas,
        float* __restrict__ out) {
    const int w = blockIdx.x * THREADS + threadIdx.x;
    if (w >= W_TOT) return;

    size_t pos;
    float  val;

    if (w < W_HEAD) {
        // conc_low / conc_up vectors (contiguous, coalesced)
        const int i = w & (NN - 1);
        const float l = lower[i];
        const float u = upper[i];
        if (w < NN) {
            const float a = fminf(fmaxf(alphas[i], 0.f), 1.f);
            const bool active   = (u > 0.f) && (l >= 0.f);
            const bool unstable = (u > 0.f) && (l < 0.f);
            val = active ? l : (unstable ? a * l : 0.f);
        } else {
            val = (u > 0.f) ? u : 0.f;
        }
        out[w] = val;
        return;
    } else if (w < W_LROW) {
        // A_up last row (bias_up), col NN -> 1.0 (contiguous, coalesced)
        const int col = w - W_HEAD;
        if (col == NN) {
            val = 1.f;
        } else {
            const float l = lower[col];
            const float u = upper[col];
            const bool unstable = (u > 0.f) && (l < 0.f);
            const float d = u - l;
            const float lam = u / ((d == 0.f) ? 1.f : d);
            val = unstable ? (-lam * l) : 0.f;
        }
        out[LR0 + (size_t)col] = val;
        return;
    } else if (w < W_DLOW) {
        // A_low diagonal (scattered, stride 8194 floats)
        const int k = w - W_LROW;
        if (k == NN) {
            val = 1.f;
        } else {
            const float l = lower[k];
            const float u = upper[k];
            const bool active   = (u > 0.f) && (l >= 0.f);
            const bool unstable = (u > 0.f) && (l < 0.f);
            const float a = fminf(fmaxf(alphas[k], 0.f), 1.f);
            val = active ? 1.f : (unstable ? a : 0.f);
        }
        pos = AB + (size_t)k * (size_t)(NP1 + 1);
    } else {
        // A_up diagonal (k = 0..NN-1; k = NN lives in the last-row segment)
        const int k = w - W_DLOW;
        const float l = lower[k];
        const float u = upper[k];
        const bool active   = (u > 0.f) && (l >= 0.f);
        const bool unstable = (u > 0.f) && (l < 0.f);
        const float d = u - l;
        const float lam = u / ((d == 0.f) ? 1.f : d);
        val = active ? 1.f : (unstable ? lam : 0.f);
        pos = AUB + (size_t)k * (size_t)(NP1 + 1);
    }

    // Scattered diagonal store: streaming hint (evict-first)
    __stcs(out + pos, val);
}

extern "C" void kernel_launch(void* const* d_in, const int* in_sizes, int n_in,
                              void* d_out, int out_size) {
    const float* lower  = (const float*)d_in[0];
    const float* upper  = (const float*)d_in[1];
    const float* alphas = (const float*)d_in[2];
    float* out = (float*)d_out;

    // Full-buffer memset from the allocation base: this exact configuration
    // is the driver's fast path (~7.4 TB/s measured in R1). Do NOT offset or
    // shrink it — R4 showed an offset/odd-tail range runs ~1.5x slower.
    cudaMemsetAsync(d_out, 0, (size_t)out_size * sizeof(float), 0);

    const int blocks = (W_TOT + THREADS - 1) / THREADS;   // 81
    relu_relax_patch<<<blocks, THREADS>>>(lower, upper, alphas, out);
}